// round 16
// baseline (speedup 1.0000x reference)
#include <cuda_runtime.h>
#include <cuda_fp16.h>
#include <stdint.h>

#define NUM_EXPERTS 8
#define HIDDEN 2048
#define INTER 1408
#define NTOK 8192

#define BM 128
#define THREADS 256
#define MAX_MTILES (NTOK/BM + NUM_EXPERTS - 1)   // 71
#define NB1 (INTER/64)     // 22
#define NB2 (HIDDEN/128)   // 16
#define NK1 (HIDDEN/32)    // 64
#define NK2 (INTER/32)     // 44
#define SA 40              // smem row stride (halfs), conflict-free ldsm

#define STG (BM*SA)
#define STG_BYTES (STG*2)
#define NSTAGE 4
#define SMEM_BYTES (2*NSTAGE*STG_BYTES)   // 81920

#define CVTB 512
#define NSEG 17
#define FUSED_GRID (MAX_MTILES*(NB1+NB2) + CVTB)   // 3210 (upper bound)

// -------- device scratch --------
__device__ int g_offsets[NUM_EXPERTS + 1];
__device__ int g_mtoff[NUM_EXPERTS + 1];
__device__ int g_perm[NTOK];
__device__ int g_done[MAX_MTILES];
__device__ int g_w2cnt;
__device__ int g_segstart[NSEG + 1];
__device__ int g_segtype[NSEG];      // 0=gemm1, 1=cvt, 2=gemm2
__device__ int g_segexp[NSEG];
__device__ __half g_w1[(size_t)NUM_EXPERTS * 2 * INTER * HIDDEN];
__device__ __half g_w2[(size_t)NUM_EXPERTS * HIDDEN * INTER];
__device__ __half g_x[(size_t)NTOK * HIDDEN];
__device__ __half g_h[(size_t)NTOK * INTER];

// -------- helpers --------
__device__ __forceinline__ uint32_t cvta_s(const void* p) {
    return (uint32_t)__cvta_generic_to_shared(p);
}
__device__ __forceinline__ void ldsm4(uint32_t& r0, uint32_t& r1,
                                      uint32_t& r2, uint32_t& r3, uint32_t addr) {
    asm volatile("ldmatrix.sync.aligned.m8n8.x4.shared.b16 {%0,%1,%2,%3},[%4];"
                 : "=r"(r0), "=r"(r1), "=r"(r2), "=r"(r3) : "r"(addr));
}
__device__ __forceinline__ void mma_f16(float c[4], const uint32_t a[4],
                                        uint32_t b0, uint32_t b1) {
    asm volatile(
        "mma.sync.aligned.m16n8k16.row.col.f32.f16.f16.f32 "
        "{%0,%1,%2,%3},{%4,%5,%6,%7},{%8,%9},{%0,%1,%2,%3};\n"
        : "+f"(c[0]), "+f"(c[1]), "+f"(c[2]), "+f"(c[3])
        : "r"(a[0]), "r"(a[1]), "r"(a[2]), "r"(a[3]), "r"(b0), "r"(b1));
}
__device__ __forceinline__ void cpa16(uint32_t s, const void* g) {
    asm volatile("cp.async.cg.shared.global [%0], [%1], 16;\n" :: "r"(s), "l"(g));
}
__device__ __forceinline__ void cp_commit() {
    asm volatile("cp.async.commit_group;\n" ::: "memory");
}
__device__ __forceinline__ void cp_wait2() {
    asm volatile("cp.async.wait_group 2;\n" ::: "memory");
}
__device__ __forceinline__ uint32_t pack2(float x, float y) {
    __half2 h = __floats2half2_rn(x, y);
    return *(uint32_t*)&h;
}
__device__ __forceinline__ uint4 pack8(float4 a, float4 b) {
    uint4 v;
    v.x = pack2(a.x, a.y); v.y = pack2(a.z, a.w);
    v.z = pack2(b.x, b.y); v.w = pack2(b.z, b.w);
    return v;
}

// -------- pre-pass: block 0 = router + schedule + flag reset; others convert --------
__global__ void k_pre(const int* __restrict__ ids,
                      const float* __restrict__ w1,
                      const float* __restrict__ tokens) {
    if (blockIdx.x == 0) {
        __shared__ int sc[NUM_EXPERTS];
        __shared__ int sb[NUM_EXPERTS];
        int t = threadIdx.x;
        if (t < MAX_MTILES) g_done[t] = 0;
        if (t == 0) g_w2cnt = 0;
        if (t < NUM_EXPERTS) sc[t] = 0;
        __syncthreads();
        for (int i = t; i < NTOK; i += THREADS) atomicAdd(&sc[ids[i]], 1);
        __syncthreads();
        if (t == 0) {
            int off = 0, moff = 0;
            int mt[NUM_EXPERTS];
            for (int e = 0; e < NUM_EXPERTS; e++) {
                g_offsets[e] = off; sb[e] = off; g_mtoff[e] = moff;
                mt[e] = (sc[e] + BM - 1) / BM;
                off  += sc[e];
                moff += mt[e];
            }
            g_offsets[NUM_EXPERTS] = off;
            g_mtoff[NUM_EXPERTS]   = moff;
            // build interleaved schedule: g1e0, cvt, {g1e, g2e-1}, g2e7
            int pos = 0, si = 0;
            g_segstart[si] = pos; g_segtype[si] = 0; g_segexp[si] = 0;
            pos += mt[0] * NB1; si++;
            g_segstart[si] = pos; g_segtype[si] = 1; g_segexp[si] = 0;
            pos += CVTB; si++;
            for (int e = 1; e < NUM_EXPERTS; e++) {
                g_segstart[si] = pos; g_segtype[si] = 0; g_segexp[si] = e;
                pos += mt[e] * NB1; si++;
                g_segstart[si] = pos; g_segtype[si] = 2; g_segexp[si] = e - 1;
                pos += mt[e - 1] * NB2; si++;
            }
            g_segstart[si] = pos; g_segtype[si] = 2; g_segexp[si] = NUM_EXPERTS - 1;
            pos += mt[NUM_EXPERTS - 1] * NB2; si++;
            g_segstart[si] = pos;   // total
        }
        __syncthreads();
        if (t < NUM_EXPERTS) sc[t] = 0;
        __syncthreads();
        for (int i = t; i < NTOK; i += THREADS) {
            int e = ids[i];
            g_perm[sb[e] + atomicAdd(&sc[e], 1)] = i;
        }
        return;
    }
    const long c_w1 = (long)NUM_EXPERTS * 2 * INTER * HIDDEN / 16;
    const long c_x  = (long)NTOK * HIDDEN / 16;
    const long total = c_w1 + c_x;
    const long stride = (long)(gridDim.x - 1) * blockDim.x;
    for (long i = (long)(blockIdx.x - 1) * blockDim.x + threadIdx.x;
         i < total; i += stride) {
        const float* src; __half* dst; long j;
        if (i < c_w1) { src = w1;     dst = g_w1; j = i; }
        else          { src = tokens; dst = g_x;  j = i - c_w1; }
        const float4* s = (const float4*)src + 4 * j;
        float4 a = s[0], b = s[1], c = s[2], d = s[3];
        uint4* o = (uint4*)dst + 2 * j;
        o[0] = pack8(a, b);
        o[1] = pack8(c, d);
    }
}

// ================= fused MoE kernel (2 CTAs/SM pinned) =================
__global__ void __launch_bounds__(THREADS, 2)
k_moe(const float* __restrict__ wts, const float* __restrict__ w2src,
      float* __restrict__ out) {
    extern __shared__ __half sm[];
    const int tid = threadIdx.x;
    const int lane = tid & 31;
    const int wid = tid >> 5;
    const int wm = wid >> 1;
    const int wn = wid & 1;

    // decode schedule segment
    const int bx = blockIdx.x;
    if (bx >= g_segstart[NSEG]) return;
    int si = 0;
    while (bx >= g_segstart[si + 1]) si++;
    const int stype = g_segtype[si];
    const int e = g_segexp[si];
    const int local = bx - g_segstart[si];

    // ---------- w2 conversion ----------
    if (stype == 1) {
        const long n16 = (long)NUM_EXPERTS * HIDDEN * INTER / 16;
        const long base = (long)local * blockDim.x + tid;
        const long stride = (long)CVTB * blockDim.x;
        for (long i = base; i < n16; i += stride) {
            const float4* s = (const float4*)w2src + 4 * i;
            float4 a = s[0], b = s[1], c = s[2], d = s[3];
            uint4* o = (uint4*)g_w2 + 2 * i;
            o[0] = pack8(a, b);
            o[1] = pack8(c, d);
        }
        __threadfence();
        __syncthreads();
        if (tid == 0) atomicAdd(&g_w2cnt, 1);
        return;
    }

    // common tile decode for this expert
    const int mt = g_mtoff[e + 1] - g_mtoff[e];
    const int NB = (stype == 0) ? NB1 : NB2;
    const int nt = local / mt;
    const int ml = local % mt;
    const int m_start = g_offsets[e] + ml * BM;
    int valid = g_offsets[e + 1] - m_start;
    if (valid > BM) valid = BM;
    if (valid <= 0) return;
    const int mtg = g_mtoff[e] + ml;

    // ---------- GEMM1 ----------
    if (stype == 0) {
        const int n0 = nt * 64;

        const int lr = tid >> 1;
        const int lc = (tid & 1) * 16;
        const int arc = (lr < valid) ? lr : (valid - 1);
        const int atok = g_perm[m_start + arc];
        const __half* aptr = g_x + (size_t)atok * HIDDEN + lc;
        const int brow = (lr < 64) ? (n0 + lr) : (INTER + n0 + lr - 64);
        const __half* bptr = g_w1 + (size_t)e * 2 * INTER * HIDDEN + (size_t)brow * HIDDEN + lc;

        const uint32_t smb = cvta_s(sm);
        const uint32_t sAst = smb + (lr * SA + lc) * 2;
        const uint32_t sBst = smb + NSTAGE * STG_BYTES + (lr * SA + lc) * 2;
        const uint32_t aBase = smb + ((wm * 32 + (lane & 15)) * SA + (lane >> 4) * 8) * 2;
        const uint32_t bBase = smb + NSTAGE * STG_BYTES +
            ((wn * 32 + ((lane >> 4) * 8) + (lane & 7)) * SA + ((lane >> 3) & 1) * 8) * 2;

        float accg[2][4][4] = {};
        float accu[2][4][4] = {};

        auto issue = [&](int kt) {
            if (kt < NK1) {
                const int st = kt & (NSTAGE - 1);
                const __half* a = aptr + kt * 32;
                const __half* b = bptr + kt * 32;
                cpa16(sAst + st * STG_BYTES,      a);
                cpa16(sAst + st * STG_BYTES + 16, a + 8);
                cpa16(sBst + st * STG_BYTES,      b);
                cpa16(sBst + st * STG_BYTES + 16, b + 8);
            }
            cp_commit();
        };

        issue(0); issue(1); issue(2);

        for (int kt = 0; kt < NK1; kt++) {
            cp_wait2();
            __syncthreads();
            issue(kt + 3);

            const int st = kt & (NSTAGE - 1);
            const uint32_t aS = aBase + st * STG_BYTES;
            const uint32_t bS = bBase + st * STG_BYTES;
#pragma unroll
            for (int ks = 0; ks < 2; ks++) {
                uint32_t a[2][4];
#pragma unroll
                for (int im = 0; im < 2; im++)
                    ldsm4(a[im][0], a[im][1], a[im][2], a[im][3],
                          aS + ((im * 16 * SA + ks * 16) << 1));
#pragma unroll
                for (int jp = 0; jp < 2; jp++) {
                    uint32_t g0, g1, g2, g3, u0, u1, u2, u3;
                    ldsm4(g0, g1, g2, g3, bS + ((jp * 16 * SA + ks * 16) << 1));
                    ldsm4(u0, u1, u2, u3, bS + (((64 + jp * 16) * SA + ks * 16) << 1));
#pragma unroll
                    for (int im = 0; im < 2; im++) {
                        mma_f16(accg[im][jp * 2],     a[im], g0, g1);
                        mma_f16(accg[im][jp * 2 + 1], a[im], g2, g3);
                        mma_f16(accu[im][jp * 2],     a[im], u0, u1);
                        mma_f16(accu[im][jp * 2 + 1], a[im], u2, u3);
                    }
                }
            }
        }

        // epilogue: silu(g)*u*wt -> g_h (fp16)
#pragma unroll
        for (int im = 0; im < 2; im++) {
#pragma unroll
            for (int half = 0; half < 2; half++) {
                const int r = wm * 32 + im * 16 + half * 8 + (lane >> 2);
                if (r < valid) {
                    const int s = m_start + r;
                    const float wt = wts[g_perm[s]];
                    __half* dst = g_h + (size_t)s * INTER + n0 + wn * 32 + (lane & 3) * 2;
#pragma unroll
                    for (int jn = 0; jn < 4; jn++) {
                        float gx = accg[im][jn][half * 2 + 0];
                        float gy = accg[im][jn][half * 2 + 1];
                        float ux = accu[im][jn][half * 2 + 0];
                        float uy = accu[im][jn][half * 2 + 1];
                        float hx = (gx / (1.0f + __expf(-gx))) * ux * wt;
                        float hy = (gy / (1.0f + __expf(-gy))) * uy * wt;
                        *(__half2*)(dst + jn * 8) = __floats2half2_rn(hx, hy);
                    }
                }
            }
        }

        __threadfence();
        __syncthreads();
        if (tid == 0) atomicAdd(&g_done[mtg], 1);
        return;
    }

    // ---------- GEMM2 ----------
    {
        const int n0 = nt * 128;

        if (tid == 0) {
            while (atomicAdd(&g_w2cnt, 0) < CVTB) __nanosleep(200);
            while (atomicAdd(&g_done[mtg], 0) < NB1) __nanosleep(200);
            __threadfence();
        }
        __syncthreads();

        const int lr = tid >> 1;
        const int lc = (tid & 1) * 16;
        const int arc = (lr < valid) ? lr : (valid - 1);
        const __half* aptr = g_h + (size_t)(m_start + arc) * INTER + lc;
        const __half* bptr = g_w2 + (size_t)e * HIDDEN * INTER + (size_t)(n0 + lr) * INTER + lc;

        const uint32_t smb = cvta_s(sm);
        const uint32_t sAst = smb + (lr * SA + lc) * 2;
        const uint32_t sBst = smb + NSTAGE * STG_BYTES + (lr * SA + lc) * 2;
        const uint32_t aBase = smb + ((wm * 32 + (lane & 15)) * SA + (lane >> 4) * 8) * 2;
        const uint32_t bBase = smb + NSTAGE * STG_BYTES +
            ((wn * 64 + ((lane >> 4) * 8) + (lane & 7)) * SA + ((lane >> 3) & 1) * 8) * 2;

        float acc[2][8][4] = {};

        auto issue = [&](int kt) {
            if (kt < NK2) {
                const int st = kt & (NSTAGE - 1);
                const __half* a = aptr + kt * 32;
                const __half* b = bptr + kt * 32;
                cpa16(sAst + st * STG_BYTES,      a);
                cpa16(sAst + st * STG_BYTES + 16, a + 8);
                cpa16(sBst + st * STG_BYTES,      b);
                cpa16(sBst + st * STG_BYTES + 16, b + 8);
            }
            cp_commit();
        };

        issue(0); issue(1); issue(2);

        for (int kt = 0; kt < NK2; kt++) {
            cp_wait2();
            __syncthreads();
            issue(kt + 3);

            const int st = kt & (NSTAGE - 1);
            const uint32_t aS = aBase + st * STG_BYTES;
            const uint32_t bS = bBase + st * STG_BYTES;
#pragma unroll
            for (int ks = 0; ks < 2; ks++) {
                uint32_t a[2][4];
#pragma unroll
                for (int im = 0; im < 2; im++)
                    ldsm4(a[im][0], a[im][1], a[im][2], a[im][3],
                          aS + ((im * 16 * SA + ks * 16) << 1));
#pragma unroll
                for (int jp = 0; jp < 4; jp++) {
                    uint32_t b0, b1, b2, b3;
                    ldsm4(b0, b1, b2, b3, bS + ((jp * 16 * SA + ks * 16) << 1));
#pragma unroll
                    for (int im = 0; im < 2; im++) {
                        mma_f16(acc[im][jp * 2],     a[im], b0, b1);
                        mma_f16(acc[im][jp * 2 + 1], a[im], b2, b3);
                    }
                }
            }
        }

#pragma unroll
        for (int im = 0; im < 2; im++) {
#pragma unroll
            for (int half = 0; half < 2; half++) {
                const int r = wm * 32 + im * 16 + half * 8 + (lane >> 2);
                if (r < valid) {
                    const int tok = g_perm[m_start + r];
                    float* dst = out + (size_t)tok * HIDDEN + n0 + wn * 64 + (lane & 3) * 2;
#pragma unroll
                    for (int jn = 0; jn < 8; jn++) {
                        float2 v;
                        v.x = acc[im][jn][half * 2 + 0];
                        v.y = acc[im][jn][half * 2 + 1];
                        *(float2*)(dst + jn * 8) = v;
                    }
                }
            }
        }
    }
}

// -------- launch --------
extern "C" void kernel_launch(void* const* d_in, const int* in_sizes, int n_in,
                              void* d_out, int out_size) {
    const float* tokens = (const float*)d_in[0];
    const int*   ids    = (const int*)d_in[1];
    const float* wts    = (const float*)d_in[2];
    const float* gu     = (const float*)d_in[3];
    const float* down   = (const float*)d_in[4];
    float* out = (float*)d_out;

    cudaFuncSetAttribute(k_moe, cudaFuncAttributeMaxDynamicSharedMemorySize, SMEM_BYTES);

    k_pre<<<148 * 16 + 1, THREADS>>>(ids, gu, tokens);
    k_moe<<<FUSED_GRID, THREADS, SMEM_BYTES>>>(wts, down, out);
}

// round 17
// speedup vs baseline: 1.0295x; 1.0295x over previous
#include <cuda_runtime.h>
#include <cuda_fp16.h>
#include <stdint.h>

#define NUM_EXPERTS 8
#define HIDDEN 2048
#define INTER 1408
#define NTOK 8192

#define BM 128
#define THREADS 256
#define MAX_MTILES (NTOK/BM + NUM_EXPERTS - 1)   // 71
#define NB1 (INTER/64)     // 22
#define NB2 (HIDDEN/128)   // 16
#define NK1 (HIDDEN/32)    // 64
#define NK2 (INTER/32)     // 44
#define SA 40              // smem row stride (halfs), conflict-free ldsm

#define STG (BM*SA)
#define STG_BYTES (STG*2)
#define NSTAGE 4
#define SMEM_BYTES (2*NSTAGE*STG_BYTES)   // 81920

#define TILE_GRID1 (MAX_MTILES*NB1)       // 1562
#define W1CVTB 148                        // leading cvt blocks in gemm1 grid

// -------- device scratch --------
__device__ int g_offsets[NUM_EXPERTS + 1];
__device__ int g_mtoff[NUM_EXPERTS + 1];
__device__ int g_perm[NTOK];
__device__ int g_w1done[NUM_EXPERTS];
__device__ __half g_w1[(size_t)NUM_EXPERTS * 2 * INTER * HIDDEN];
__device__ __half g_w2[(size_t)NUM_EXPERTS * HIDDEN * INTER];
__device__ __half g_x[(size_t)NTOK * HIDDEN];    // fp16 tokens, ORIGINAL order
__device__ __half g_h[(size_t)NTOK * INTER];

// -------- helpers --------
__device__ __forceinline__ uint32_t cvta_s(const void* p) {
    return (uint32_t)__cvta_generic_to_shared(p);
}
__device__ __forceinline__ void ldsm4(uint32_t& r0, uint32_t& r1,
                                      uint32_t& r2, uint32_t& r3, uint32_t addr) {
    asm volatile("ldmatrix.sync.aligned.m8n8.x4.shared.b16 {%0,%1,%2,%3},[%4];"
                 : "=r"(r0), "=r"(r1), "=r"(r2), "=r"(r3) : "r"(addr));
}
__device__ __forceinline__ void mma_f16(float c[4], const uint32_t a[4],
                                        uint32_t b0, uint32_t b1) {
    asm volatile(
        "mma.sync.aligned.m16n8k16.row.col.f32.f16.f16.f32 "
        "{%0,%1,%2,%3},{%4,%5,%6,%7},{%8,%9},{%0,%1,%2,%3};\n"
        : "+f"(c[0]), "+f"(c[1]), "+f"(c[2]), "+f"(c[3])
        : "r"(a[0]), "r"(a[1]), "r"(a[2]), "r"(a[3]), "r"(b0), "r"(b1));
}
__device__ __forceinline__ void cpa16(uint32_t s, const void* g) {
    asm volatile("cp.async.cg.shared.global [%0], [%1], 16;\n" :: "r"(s), "l"(g));
}
__device__ __forceinline__ void cp_commit() {
    asm volatile("cp.async.commit_group;\n" ::: "memory");
}
__device__ __forceinline__ void cp_wait2() {
    asm volatile("cp.async.wait_group 2;\n" ::: "memory");
}
__device__ __forceinline__ uint32_t pack2(float x, float y) {
    __half2 h = __floats2half2_rn(x, y);
    return *(uint32_t*)&h;
}
__device__ __forceinline__ uint4 pack8(float4 a, float4 b) {
    uint4 v;
    v.x = pack2(a.x, a.y); v.y = pack2(a.z, a.w);
    v.z = pack2(b.x, b.y); v.w = pack2(b.z, b.w);
    return v;
}

// -------- pre-pass: block 0 = router + flag reset; others convert tokens + w1[e0] --------
__global__ void k_pre(const int* __restrict__ ids,
                      const float* __restrict__ w1,
                      const float* __restrict__ tokens) {
    if (blockIdx.x == 0) {
        __shared__ int sc[NUM_EXPERTS];
        __shared__ int sb[NUM_EXPERTS];
        int t = threadIdx.x;
        if (t < NUM_EXPERTS) g_w1done[t] = 0;
        if (t < NUM_EXPERTS) sc[t] = 0;
        __syncthreads();
        for (int i = t; i < NTOK; i += THREADS) atomicAdd(&sc[ids[i]], 1);
        __syncthreads();
        if (t == 0) {
            int off = 0, moff = 0;
            for (int e = 0; e < NUM_EXPERTS; e++) {
                g_offsets[e] = off; sb[e] = off; g_mtoff[e] = moff;
                off  += sc[e];
                moff += (sc[e] + BM - 1) / BM;
            }
            g_offsets[NUM_EXPERTS] = off;
            g_mtoff[NUM_EXPERTS]   = moff;
        }
        __syncthreads();
        if (t < NUM_EXPERTS) sc[t] = 0;
        __syncthreads();
        for (int i = t; i < NTOK; i += THREADS) {
            int e = ids[i];
            g_perm[sb[e] + atomicAdd(&sc[e], 1)] = i;
        }
        return;
    }
    // convert w1 expert 0 + all tokens
    const long c_e0 = (long)2 * INTER * HIDDEN / 16;
    const long c_x  = (long)NTOK * HIDDEN / 16;
    const long total = c_e0 + c_x;
    const long stride = (long)(gridDim.x - 1) * blockDim.x;
    for (long i = (long)(blockIdx.x - 1) * blockDim.x + threadIdx.x;
         i < total; i += stride) {
        const float* src; __half* dst; long j;
        if (i < c_e0) { src = w1;     dst = g_w1; j = i; }
        else          { src = tokens; dst = g_x;  j = i - c_e0; }
        const float4* s = (const float4*)src + 4 * j;
        float4 a = s[0], b = s[1], c = s[2], d = s[3];
        uint4* o = (uint4*)dst + 2 * j;
        o[0] = pack8(a, b);
        o[1] = pack8(c, d);
    }
}

__device__ __forceinline__ bool decode_tile(int bx, int NB,
        int& e, int& nt, int& m_start, int& valid) {
    int total = g_mtoff[NUM_EXPERTS] * NB;
    if (bx >= total) return false;
    e = 0;
    while (bx >= g_mtoff[e + 1] * NB) e++;
    int local = bx - g_mtoff[e] * NB;
    int mt = g_mtoff[e + 1] - g_mtoff[e];
    nt = local / mt;
    int ml = local % mt;
    m_start = g_offsets[e] + ml * BM;
    valid = g_offsets[e + 1] - m_start;
    if (valid > BM) valid = BM;
    return true;
}

// ================= GEMM1 (+ lazy w1[e1..e7] and w2 conversion in leading blocks) =================
__global__ void __launch_bounds__(THREADS, 2)
k_gemm1(const float* __restrict__ wts,
        const float* __restrict__ w1src,
        const float* __restrict__ w2src) {
    extern __shared__ __half sm[];
    const int tid = threadIdx.x;

    // ---------- leading blocks: convert w1 e1..e7 (sequentially), then w2 ----------
    if (blockIdx.x < W1CVTB) {
        const long per = (long)2 * INTER * HIDDEN / 16;   // chunks per expert
        const long stride = (long)W1CVTB * blockDim.x;
        for (int ee = 1; ee < NUM_EXPERTS; ee++) {
            const float* src = w1src + (size_t)ee * 2 * INTER * HIDDEN;
            __half* dst = g_w1 + (size_t)ee * 2 * INTER * HIDDEN;
            for (long i = (long)blockIdx.x * blockDim.x + tid; i < per; i += stride) {
                const float4* s = (const float4*)src + 4 * i;
                float4 a = s[0], b = s[1], c = s[2], d = s[3];
                uint4* o = (uint4*)dst + 2 * i;
                o[0] = pack8(a, b);
                o[1] = pack8(c, d);
            }
            __threadfence();
            __syncthreads();
            if (tid == 0) atomicAdd(&g_w1done[ee], 1);
        }
        // w2: no flag needed — gemm2 launches after this kernel completes
        const long c_w2 = (long)NUM_EXPERTS * HIDDEN * INTER / 16;
        for (long i = (long)blockIdx.x * blockDim.x + tid; i < c_w2; i += stride) {
            const float4* s = (const float4*)w2src + 4 * i;
            float4 a = s[0], b = s[1], c = s[2], d = s[3];
            uint4* o = (uint4*)g_w2 + 2 * i;
            o[0] = pack8(a, b);
            o[1] = pack8(c, d);
        }
        return;
    }

    int e, nt, m_start, valid;
    if (!decode_tile(blockIdx.x - W1CVTB, NB1, e, nt, m_start, valid)) return;

    // wait until this expert's w1 is converted (e0 done in k_pre)
    if (e > 0) {
        if (tid == 0) {
            while (atomicAdd(&g_w1done[e], 0) < W1CVTB) __nanosleep(200);
            __threadfence();
        }
        __syncthreads();
    }

    const int lane = tid & 31;
    const int wid = tid >> 5;
    const int wm = wid >> 1;
    const int wn = wid & 1;
    const int n0 = nt * 64;

    const int lr = tid >> 1;
    const int lc = (tid & 1) * 16;
    const int arc = (lr < valid) ? lr : (valid - 1);
    const int atok = g_perm[m_start + arc];
    const __half* aptr = g_x + (size_t)atok * HIDDEN + lc;
    const int brow = (lr < 64) ? (n0 + lr) : (INTER + n0 + lr - 64);
    const __half* bptr = g_w1 + (size_t)e * 2 * INTER * HIDDEN + (size_t)brow * HIDDEN + lc;

    const uint32_t smb = cvta_s(sm);
    const uint32_t sAst = smb + (lr * SA + lc) * 2;
    const uint32_t sBst = smb + NSTAGE * STG_BYTES + (lr * SA + lc) * 2;
    const uint32_t aBase = smb + ((wm * 32 + (lane & 15)) * SA + (lane >> 4) * 8) * 2;
    const uint32_t bBase = smb + NSTAGE * STG_BYTES +
        ((wn * 32 + ((lane >> 4) * 8) + (lane & 7)) * SA + ((lane >> 3) & 1) * 8) * 2;

    float accg[2][4][4] = {};
    float accu[2][4][4] = {};

    auto issue = [&](int kt) {
        if (kt < NK1) {
            const int st = kt & (NSTAGE - 1);
            const __half* a = aptr + kt * 32;
            const __half* b = bptr + kt * 32;
            cpa16(sAst + st * STG_BYTES,      a);
            cpa16(sAst + st * STG_BYTES + 16, a + 8);
            cpa16(sBst + st * STG_BYTES,      b);
            cpa16(sBst + st * STG_BYTES + 16, b + 8);
        }
        cp_commit();
    };

    issue(0); issue(1); issue(2);

    for (int kt = 0; kt < NK1; kt++) {
        cp_wait2();
        __syncthreads();
        issue(kt + 3);

        const int st = kt & (NSTAGE - 1);
        const uint32_t aS = aBase + st * STG_BYTES;
        const uint32_t bS = bBase + st * STG_BYTES;
#pragma unroll
        for (int ks = 0; ks < 2; ks++) {
            uint32_t a[2][4];
#pragma unroll
            for (int im = 0; im < 2; im++)
                ldsm4(a[im][0], a[im][1], a[im][2], a[im][3],
                      aS + ((im * 16 * SA + ks * 16) << 1));
#pragma unroll
            for (int jp = 0; jp < 2; jp++) {
                uint32_t g0, g1, g2, g3, u0, u1, u2, u3;
                ldsm4(g0, g1, g2, g3, bS + ((jp * 16 * SA + ks * 16) << 1));
                ldsm4(u0, u1, u2, u3, bS + (((64 + jp * 16) * SA + ks * 16) << 1));
#pragma unroll
                for (int im = 0; im < 2; im++) {
                    mma_f16(accg[im][jp * 2],     a[im], g0, g1);
                    mma_f16(accg[im][jp * 2 + 1], a[im], g2, g3);
                    mma_f16(accu[im][jp * 2],     a[im], u0, u1);
                    mma_f16(accu[im][jp * 2 + 1], a[im], u2, u3);
                }
            }
        }
    }

    // epilogue: silu(g)*u*wt -> g_h (fp16)
#pragma unroll
    for (int im = 0; im < 2; im++) {
#pragma unroll
        for (int half = 0; half < 2; half++) {
            const int r = wm * 32 + im * 16 + half * 8 + (lane >> 2);
            if (r < valid) {
                const int s = m_start + r;
                const float wt = wts[g_perm[s]];
                __half* dst = g_h + (size_t)s * INTER + n0 + wn * 32 + (lane & 3) * 2;
#pragma unroll
                for (int jn = 0; jn < 4; jn++) {
                    float gx = accg[im][jn][half * 2 + 0];
                    float gy = accg[im][jn][half * 2 + 1];
                    float ux = accu[im][jn][half * 2 + 0];
                    float uy = accu[im][jn][half * 2 + 1];
                    float hx = (gx / (1.0f + __expf(-gx))) * ux * wt;
                    float hy = (gy / (1.0f + __expf(-gy))) * uy * wt;
                    *(__half2*)(dst + jn * 8) = __floats2half2_rn(hx, hy);
                }
            }
        }
    }
}

// ================= GEMM2 (BN=128) — R13 verbatim + pin =================
__global__ void __launch_bounds__(THREADS, 2)
k_gemm2(float* __restrict__ out) {
    extern __shared__ __half sm[];

    int e, nt, m_start, valid;
    if (!decode_tile(blockIdx.x, NB2, e, nt, m_start, valid)) return;

    const int tid = threadIdx.x;
    const int lane = tid & 31;
    const int wid = tid >> 5;
    const int wm = wid >> 1;
    const int wn = wid & 1;
    const int n0 = nt * 128;

    const int lr = tid >> 1;
    const int lc = (tid & 1) * 16;
    const int arc = (lr < valid) ? lr : (valid - 1);
    const __half* aptr = g_h + (size_t)(m_start + arc) * INTER + lc;
    const __half* bptr = g_w2 + (size_t)e * HIDDEN * INTER + (size_t)(n0 + lr) * INTER + lc;

    const uint32_t smb = cvta_s(sm);
    const uint32_t sAst = smb + (lr * SA + lc) * 2;
    const uint32_t sBst = smb + NSTAGE * STG_BYTES + (lr * SA + lc) * 2;
    const uint32_t aBase = smb + ((wm * 32 + (lane & 15)) * SA + (lane >> 4) * 8) * 2;
    const uint32_t bBase = smb + NSTAGE * STG_BYTES +
        ((wn * 64 + ((lane >> 4) * 8) + (lane & 7)) * SA + ((lane >> 3) & 1) * 8) * 2;

    float acc[2][8][4] = {};

    auto issue = [&](int kt) {
        if (kt < NK2) {
            const int st = kt & (NSTAGE - 1);
            const __half* a = aptr + kt * 32;
            const __half* b = bptr + kt * 32;
            cpa16(sAst + st * STG_BYTES,      a);
            cpa16(sAst + st * STG_BYTES + 16, a + 8);
            cpa16(sBst + st * STG_BYTES,      b);
            cpa16(sBst + st * STG_BYTES + 16, b + 8);
        }
        cp_commit();
    };

    issue(0); issue(1); issue(2);

    for (int kt = 0; kt < NK2; kt++) {
        cp_wait2();
        __syncthreads();
        issue(kt + 3);

        const int st = kt & (NSTAGE - 1);
        const uint32_t aS = aBase + st * STG_BYTES;
        const uint32_t bS = bBase + st * STG_BYTES;
#pragma unroll
        for (int ks = 0; ks < 2; ks++) {
            uint32_t a[2][4];
#pragma unroll
            for (int im = 0; im < 2; im++)
                ldsm4(a[im][0], a[im][1], a[im][2], a[im][3],
                      aS + ((im * 16 * SA + ks * 16) << 1));
#pragma unroll
            for (int jp = 0; jp < 4; jp++) {
                uint32_t b0, b1, b2, b3;
                ldsm4(b0, b1, b2, b3, bS + ((jp * 16 * SA + ks * 16) << 1));
#pragma unroll
                for (int im = 0; im < 2; im++) {
                    mma_f16(acc[im][jp * 2],     a[im], b0, b1);
                    mma_f16(acc[im][jp * 2 + 1], a[im], b2, b3);
                }
            }
        }
    }

#pragma unroll
    for (int im = 0; im < 2; im++) {
#pragma unroll
        for (int half = 0; half < 2; half++) {
            const int r = wm * 32 + im * 16 + half * 8 + (lane >> 2);
            if (r < valid) {
                const int tok = g_perm[m_start + r];
                float* dst = out + (size_t)tok * HIDDEN + n0 + wn * 64 + (lane & 3) * 2;
#pragma unroll
                for (int jn = 0; jn < 8; jn++) {
                    float2 v;
                    v.x = acc[im][jn][half * 2 + 0];
                    v.y = acc[im][jn][half * 2 + 1];
                    *(float2*)(dst + jn * 8) = v;
                }
            }
        }
    }
}

// -------- launch --------
extern "C" void kernel_launch(void* const* d_in, const int* in_sizes, int n_in,
                              void* d_out, int out_size) {
    const float* tokens = (const float*)d_in[0];
    const int*   ids    = (const int*)d_in[1];
    const float* wts    = (const float*)d_in[2];
    const float* gu     = (const float*)d_in[3];
    const float* down   = (const float*)d_in[4];
    float* out = (float*)d_out;

    cudaFuncSetAttribute(k_gemm1, cudaFuncAttributeMaxDynamicSharedMemorySize, SMEM_BYTES);
    cudaFuncSetAttribute(k_gemm2, cudaFuncAttributeMaxDynamicSharedMemorySize, SMEM_BYTES);

    k_pre<<<148 * 8 + 1, THREADS>>>(ids, gu, tokens);

    k_gemm1<<<W1CVTB + TILE_GRID1, THREADS, SMEM_BYTES>>>(wts, gu, down);
    k_gemm2<<<MAX_MTILES * NB2, THREADS, SMEM_BYTES>>>(out);
}